// round 15
// baseline (speedup 1.0000x reference)
#include <cuda_runtime.h>
#include <cuda_fp16.h>
#include <cstdint>

#define NPv 50000
#define NAv 50000
#define Dv  128
#define Emax 800000
#define NCHUNK 196   // ceil(50000/256)

// ---------------- scratch ----------------
__device__ float g_agg1[(size_t)NPv * Dv];
__device__ float g_agg2[(size_t)NPv * Dv];
__device__ float g_agg3[(size_t)NAv * Dv];
__device__ float g_z1[(size_t)NPv * Dv];
__device__ float g_z2[(size_t)NPv * Dv];
__device__ float g_z3[(size_t)NAv * Dv];
__device__ __half g_h16[(size_t)(NPv + NAv) * Dv];   // [paper | author] fp16 table
__device__ float g_deg[6 * 50000];                   // RAW counts
__device__ float g_stats[7 * 128];
__device__ float g_wsum[2];
__device__ float g_beta[2];
__device__ float g_scale_p[128], g_shift_p[128];
__device__ float g_scale_a[128], g_shift_a[128];
__device__ int   g_ebuf[3][Emax];                    // dst-sorted src ids (CSR)
__device__ int   g_soffs[3][50000];                  // post-fill: segment END offsets
__device__ int   g_csum[3][NCHUNK];

// ---------------- fp16 mma helper ----------------
__device__ __forceinline__ void mma_f16(float4& d, const uint32_t a[4],
                                        uint32_t b0, uint32_t b1) {
    asm volatile(
        "mma.sync.aligned.m16n8k16.row.col.f32.f16.f16.f32 "
        "{%0,%1,%2,%3},{%4,%5,%6,%7},{%8,%9},{%0,%1,%2,%3};"
        : "+f"(d.x), "+f"(d.y), "+f"(d.z), "+f"(d.w)
        : "r"(a[0]), "r"(a[1]), "r"(a[2]), "r"(a[3]), "r"(b0), "r"(b1));
}
__device__ __forceinline__ uint32_t h2bits(__half2 h) {
    return *(uint32_t*)&h;
}

// ---------------- zero scratch (deg/stats/wsum only) ----------------
__global__ void zero_kernel() {
    int i = blockIdx.x * blockDim.x + threadIdx.x;
    float4 z = make_float4(0.f, 0.f, 0.f, 0.f);
    if (i < (6 * 50000) / 4) ((float4*)g_deg)[i] = z;
    if (i < (7 * 128) / 4) ((float4*)g_stats)[i] = z;
    if (i < 2) g_wsum[i] = 0.f;
}

// ---------------- fp32 -> fp16 feature table ----------------
__global__ void h2half_kernel(const float* __restrict__ hp, const float* __restrict__ ha) {
    size_t i = (size_t)blockIdx.x * blockDim.x + threadIdx.x;   // unit = 8 elems
    const size_t n8 = (size_t)NPv * Dv / 8;
    const float* srcB;
    size_t j;
    if (i < n8) { srcB = hp; j = i; }
    else if (i < 2 * n8) { srcB = ha; j = i - n8; }
    else return;
    float4 a = ((const float4*)srcB)[2 * j];
    float4 b = ((const float4*)srcB)[2 * j + 1];
    __half2 p0 = __floats2half2_rn(a.x, a.y);
    __half2 p1 = __floats2half2_rn(a.z, a.w);
    __half2 p2 = __floats2half2_rn(b.x, b.y);
    __half2 p3 = __floats2half2_rn(b.z, b.w);
    uint4 o;
    o.x = h2bits(p0); o.y = h2bits(p1);
    o.z = h2bits(p2); o.w = h2bits(p3);
    ((uint4*)g_h16)[i] = o;
}

// ---------------- degrees (raw counts) ----------------
__global__ void degree_kernel(const int* __restrict__ s1, const int* __restrict__ d1,
                              const int* __restrict__ s2, const int* __restrict__ d2,
                              const int* __restrict__ s3, const int* __restrict__ d3,
                              int nE) {
    int i = blockIdx.x * blockDim.x + threadIdx.x;
    if (i >= nE) return;
    atomicAdd(&g_deg[0 * 50000 + s1[i]], 1.0f);
    atomicAdd(&g_deg[1 * 50000 + d1[i]], 1.0f);
    atomicAdd(&g_deg[2 * 50000 + s2[i]], 1.0f);
    atomicAdd(&g_deg[3 * 50000 + d2[i]], 1.0f);
    atomicAdd(&g_deg[4 * 50000 + s3[i]], 1.0f);
    atomicAdd(&g_deg[5 * 50000 + d3[i]], 1.0f);
}

// -------- chunked exclusive scan of deg_in (3 phases) ------------------------
__global__ __launch_bounds__(256) void prefix1_kernel(int M) {
    int r = blockIdx.y, b = blockIdx.x, t = threadIdx.x;
    int n = b * 256 + t;
    int iv = 0;
    if (n < M) iv = (int)(g_deg[(2 * r + 1) * 50000 + n] + 0.5f);
    __shared__ int sh[256];
    sh[t] = iv;
    __syncthreads();
#pragma unroll
    for (int o = 128; o > 0; o >>= 1) {
        if (t < o) sh[t] += sh[t + o];
        __syncthreads();
    }
    if (t == 0) g_csum[r][b] = sh[0];
}

__global__ __launch_bounds__(256) void prefix2_kernel(int nb) {
    int r = blockIdx.x, t = threadIdx.x;
    __shared__ int sh[256];
    int v = (t < nb) ? g_csum[r][t] : 0;
    sh[t] = v;
    __syncthreads();
#pragma unroll
    for (int o = 1; o < 256; o <<= 1) {
        int u = (t >= o) ? sh[t - o] : 0;
        __syncthreads();
        sh[t] += u;
        __syncthreads();
    }
    if (t < nb) g_csum[r][t] = sh[t] - v;   // exclusive
}

__global__ __launch_bounds__(256) void prefix3_kernel(int M) {
    int r = blockIdx.y, b = blockIdx.x, t = threadIdx.x;
    int n = b * 256 + t;
    int iv = 0;
    if (n < M) iv = (int)(g_deg[(2 * r + 1) * 50000 + n] + 0.5f);
    __shared__ int sh[256];
    sh[t] = iv;
    __syncthreads();
#pragma unroll
    for (int o = 1; o < 256; o <<= 1) {
        int u = (t >= o) ? sh[t - o] : 0;
        __syncthreads();
        sh[t] += u;
        __syncthreads();
    }
    if (n < M) g_soffs[r][n] = sh[t] - iv + g_csum[r][b];
}

// ---------------- fill: dst-grouped src lists (CSR) ----------------
__global__ void fill_kernel(const int* __restrict__ s1, const int* __restrict__ d1,
                            const int* __restrict__ s2, const int* __restrict__ d2,
                            const int* __restrict__ s3, const int* __restrict__ d3,
                            int nE) {
    int r = blockIdx.y;
    const int* src = r == 0 ? s1 : r == 1 ? s2 : s3;
    const int* dst = r == 0 ? d1 : r == 1 ? d2 : d3;
    int i = blockIdx.x * blockDim.x + threadIdx.x;
    if (i >= nE) return;
    int sV = src[i], dV = dst[i];
    int pos = atomicAdd(&g_soffs[r][dV], 1);
    g_ebuf[r][pos] = sV;
}
// After fill: g_soffs[r][d] == END offset of dst d's segment.

// --- scatter: warp per dst row, 8-edge chunks (MLP=8), single STG.128 --------
__global__ __launch_bounds__(256) void scatter_kernel(int M) {
    int rel = blockIdx.y;
    const int* eb = g_ebuf[rel];
    const __half* H = (rel == 1) ? g_h16 : g_h16 + (size_t)NPv * Dv;
    const float* degout = g_deg + (2 * rel) * 50000;         // raw out-degree
    const float* degin = g_deg + (2 * rel + 1) * 50000;      // raw in-degree
    float* agg = (rel == 0) ? g_agg1 : (rel == 1) ? g_agg2 : g_agg3;

    int dst = (blockIdx.x * blockDim.x + threadIdx.x) >> 5;
    int lane = threadIdx.x & 31;
    if (dst >= M) return;

    int end = __ldg(&g_soffs[rel][dst]);
    int deg = (int)(__ldg(degin + dst) + 0.5f);
    int start = end - deg;

    float4 acc = make_float4(0.f, 0.f, 0.f, 0.f);
    for (int e = start; e < end; e += 8) {
        int m = min(8, end - e);
        int s[8];
#pragma unroll
        for (int i = 0; i < 8; i++) s[i] = __ldg(eb + min(e + i, end - 1));
        float sc[8];
#pragma unroll
        for (int i = 0; i < 8; i++) sc[i] = rsqrtf(fmaxf(__ldg(degout + s[i]), 1.0f));
        uint2 raw[8];
#pragma unroll
        for (int i = 0; i < 8; i++)
            raw[i] = *((const uint2*)(H + (size_t)s[i] * Dv) + lane);   // MLP=8
#pragma unroll
        for (int i = 0; i < 8; i++) {
            if (i < m) {
                float2 f01 = __half22float2(*(const __half2*)&raw[i].x);
                float2 f23 = __half22float2(*(const __half2*)&raw[i].y);
                float c = sc[i];
                acc.x += f01.x * c;
                acc.y += f01.y * c;
                acc.z += f23.x * c;
                acc.w += f23.y * c;
            }
        }
    }
    *((float4*)(agg + (size_t)dst * Dv) + lane) = acc;   // one plain store
}

// ===== FP16 GEMM core: 128x128 tile, m16n8k16, DOUBLE-BUFFERED smem ==========
#define GEMM_PROLOGUE()                                                        \
    __shared__ __half As[2][128][40];                                          \
    __shared__ __half2 Ws2[2][16][136];                                        \
    const int tid = threadIdx.x;                                               \
    const int wid = tid >> 5, lane = tid & 31;                                 \
    const int grp = lane >> 2, tig = lane & 3;                                 \
    const int rowBase = blockIdx.x * 128;                                      \
    const int rowOff = (wid & 3) * 32;                                         \
    const int colOff = (wid >> 2) * 64;                                        \
    float4 acc[2][8];                                                          \
    _Pragma("unroll") for (int ms = 0; ms < 2; ms++)                           \
        _Pragma("unroll") for (int ns = 0; ns < 8; ns++)                       \
            acc[ms][ns] = make_float4(0.f, 0.f, 0.f, 0.f);

#define LOAD_CHUNK(kc)                                                         \
    _Pragma("unroll") for (int j = 0; j < 4; j++) {                            \
        int i = tid + 256 * j;                                                 \
        int r = i >> 3, c4 = (i & 7) << 2;                                     \
        int gr = min(rowBase + r, M - 1);                                      \
        aPre[j] = *(const float4*)(A + (size_t)gr * 128 + (kc) * 32 + c4);     \
    }                                                                          \
    _Pragma("unroll") for (int jj = 0; jj < 2; jj++) {                         \
        int u = tid + 256 * jj;                                                \
        int k2 = u >> 5, n4 = (u & 31) << 2;                                   \
        wA[jj] = *(const float4*)(W + (size_t)((kc) * 32 + 2 * k2) * 128 + n4);     \
        wB[jj] = *(const float4*)(W + (size_t)((kc) * 32 + 2 * k2 + 1) * 128 + n4); \
    }

#define STORE_CHUNK(buf)                                                       \
    _Pragma("unroll") for (int j = 0; j < 4; j++) {                            \
        int i = tid + 256 * j;                                                 \
        int r = i >> 3, c4 = (i & 7) << 2;                                     \
        uint2 ta;                                                              \
        ta.x = h2bits(__floats2half2_rn(aPre[j].x, aPre[j].y));                \
        ta.y = h2bits(__floats2half2_rn(aPre[j].z, aPre[j].w));                \
        *(uint2*)&As[buf][r][c4] = ta;                                         \
    }                                                                          \
    _Pragma("unroll") for (int jj = 0; jj < 2; jj++) {                         \
        int u = tid + 256 * jj;                                                \
        int k2 = u >> 5, n4 = (u & 31) << 2;                                   \
        uint4 tw;                                                              \
        tw.x = h2bits(__halves2half2(__float2half_rn(wA[jj].x), __float2half_rn(wB[jj].x))); \
        tw.y = h2bits(__halves2half2(__float2half_rn(wA[jj].y), __float2half_rn(wB[jj].y))); \
        tw.z = h2bits(__halves2half2(__float2half_rn(wA[jj].z), __float2half_rn(wB[jj].z))); \
        tw.w = h2bits(__halves2half2(__float2half_rn(wA[jj].w), __float2half_rn(wB[jj].w))); \
        *(uint4*)&Ws2[buf][k2][n4] = tw;                                       \
    }

#define MMA_CHUNK(buf)                                                         \
    _Pragma("unroll") for (int ks = 0; ks < 2; ks++) {                         \
        int k0 = ks * 16;                                                      \
        uint32_t a[2][4];                                                      \
        _Pragma("unroll") for (int ms = 0; ms < 2; ms++) {                     \
            int r = rowOff + ms * 16 + grp;                                    \
            a[ms][0] = *(const uint32_t*)&As[buf][r][k0 + 2 * tig];            \
            a[ms][1] = *(const uint32_t*)&As[buf][r + 8][k0 + 2 * tig];        \
            a[ms][2] = *(const uint32_t*)&As[buf][r][k0 + 8 + 2 * tig];        \
            a[ms][3] = *(const uint32_t*)&As[buf][r + 8][k0 + 8 + 2 * tig];    \
        }                                                                      \
        _Pragma("unroll") for (int ns = 0; ns < 8; ns++) {                     \
            int cn = colOff + ns * 8 + grp;                                    \
            uint32_t b0 = h2bits(Ws2[buf][ks * 8 + tig][cn]);                  \
            uint32_t b1 = h2bits(Ws2[buf][ks * 8 + 4 + tig][cn]);              \
            mma_f16(acc[0][ns], a[0], b0, b1);                                 \
            mma_f16(acc[1][ns], a[1], b0, b1);                                 \
        }                                                                      \
    }

// Double-buffered: one __syncthreads per K-chunk.
#define GEMM_MAINLOOP()                                                        \
    float4 aPre[4], wA[2], wB[2];                                              \
    LOAD_CHUNK(0)                                                              \
    STORE_CHUNK(0)                                                             \
    __syncthreads();                                                           \
    _Pragma("unroll") for (int kc = 0; kc < 4; kc++) {                         \
        if (kc < 3) { LOAD_CHUNK(kc + 1) }                                     \
        MMA_CHUNK(kc & 1)                                                      \
        if (kc < 3) {                                                          \
            STORE_CHUNK((kc + 1) & 1)                                          \
            __syncthreads();                                                   \
        }                                                                      \
    }

// conv GEMM: C = (A @ W) * rsqrt(max(deg_in,1)); blockIdx.y = relation
__global__ __launch_bounds__(256, 2) void conv_gemm_f16(
    const float* __restrict__ A1, const float* __restrict__ A2, const float* __restrict__ A3,
    const float* __restrict__ W1, const float* __restrict__ W2, const float* __restrict__ W3,
    const float* __restrict__ rs1, const float* __restrict__ rs2, const float* __restrict__ rs3,
    float* __restrict__ C1, float* __restrict__ C2, float* __restrict__ C3, int M) {
    const int rel = blockIdx.y;
    const float* A = rel == 0 ? A1 : rel == 1 ? A2 : A3;
    const float* W = rel == 0 ? W1 : rel == 1 ? W2 : W3;
    const float* rs = rel == 0 ? rs1 : rel == 1 ? rs2 : rs3;   // raw deg_in
    float* C = rel == 0 ? C1 : rel == 1 ? C2 : C3;

    GEMM_PROLOGUE()
    GEMM_MAINLOOP()

#pragma unroll
    for (int ms = 0; ms < 2; ms++) {
        int rA = rowBase + rowOff + ms * 16 + grp;
        int rB = rA + 8;
        float sA = (rA < M) ? rsqrtf(fmaxf(rs[rA], 1.0f)) : 0.f;
        float sB = (rB < M) ? rsqrtf(fmaxf(rs[rB], 1.0f)) : 0.f;
#pragma unroll
        for (int ns = 0; ns < 8; ns++) {
            int cC = colOff + ns * 8 + 2 * tig;
            if (rA < M) {
                float2 o = make_float2(acc[ms][ns].x * sA, acc[ms][ns].y * sA);
                *(float2*)(C + (size_t)rA * 128 + cC) = o;
            }
            if (rB < M) {
                float2 o = make_float2(acc[ms][ns].z * sB, acc[ms][ns].w * sB);
                *(float2*)(C + (size_t)rB * 128 + cC) = o;
            }
        }
    }
}

__global__ __launch_bounds__(256, 2) void att_gemm_f16(
    const float* __restrict__ Z1, const float* __restrict__ Z2,
    const float* __restrict__ W,
    const float* __restrict__ bb, const float* __restrict__ qq,
    float* __restrict__ wsum, int M) {
    const float* A = blockIdx.y == 0 ? Z1 : Z2;

    GEMM_PROLOGUE()
    GEMM_MAINLOOP()

    float p = 0.f;
#pragma unroll
    for (int ms = 0; ms < 2; ms++) {
        int rA = rowBase + rowOff + ms * 16 + grp;
        int rB = rA + 8;
#pragma unroll
        for (int ns = 0; ns < 8; ns++) {
            int cC = colOff + ns * 8 + 2 * tig;
            float b0v = __ldg(bb + cC), b1v = __ldg(bb + cC + 1);
            float q0v = __ldg(qq + cC), q1v = __ldg(qq + cC + 1);
            if (rA < M)
                p += tanhf(acc[ms][ns].x + b0v) * q0v + tanhf(acc[ms][ns].y + b1v) * q1v;
            if (rB < M)
                p += tanhf(acc[ms][ns].z + b0v) * q0v + tanhf(acc[ms][ns].w + b1v) * q1v;
        }
    }
#pragma unroll
    for (int o = 16; o > 0; o >>= 1) p += __shfl_xor_sync(0xffffffffu, p, o);
    if (lane == 0) atomicAdd(wsum + blockIdx.y, p);
}

// ---------------- column moments (merged: y=0 paper, y=1 author) -------------
__global__ __launch_bounds__(128) void stats_kernel(
    const float* __restrict__ z1, const float* __restrict__ z2,
    const float* __restrict__ z3, int MP, int MA) {
    int c = threadIdx.x;
    if (blockIdx.y == 0) {
        int r0 = blockIdx.x * 128;
        int r1 = min(r0 + 128, MP);
        if (r0 >= MP) return;
        float s1 = 0.f, s2 = 0.f, q1 = 0.f, q2 = 0.f, cx = 0.f;
        for (int r = r0; r < r1; r++) {
            float v1 = z1[(size_t)r * 128 + c];
            float v2 = z2[(size_t)r * 128 + c];
            s1 += v1; s2 += v2; q1 += v1 * v1; q2 += v2 * v2; cx += v1 * v2;
        }
        atomicAdd(&g_stats[0 * 128 + c], s1);
        atomicAdd(&g_stats[1 * 128 + c], s2);
        atomicAdd(&g_stats[2 * 128 + c], q1);
        atomicAdd(&g_stats[3 * 128 + c], q2);
        atomicAdd(&g_stats[4 * 128 + c], cx);
    } else {
        int r0 = blockIdx.x * 128;
        int r1 = min(r0 + 128, MA);
        if (r0 >= MA) return;
        float s3 = 0.f, q3 = 0.f;
        for (int r = r0; r < r1; r++) {
            float v = z3[(size_t)r * 128 + c];
            s3 += v; q3 += v * v;
        }
        atomicAdd(&g_stats[5 * 128 + c], s3);
        atomicAdd(&g_stats[6 * 128 + c], q3);
    }
}

// ---------------- finalize ----------------
__global__ void finalize_kernel(const float* __restrict__ gamma, const float* __restrict__ betaBN,
                                int MP, int MA) {
    int j = threadIdx.x;
    float w1 = g_wsum[0] / (float)MP;
    float w2 = g_wsum[1] / (float)MP;
    float m = fmaxf(w1, w2);
    float e1 = expf(w1 - m), e2 = expf(w2 - m);
    float b1 = e1 / (e1 + e2), b2 = e2 / (e1 + e2);
    if (j == 0) { g_beta[0] = b1; g_beta[1] = b2; }

    float S1 = g_stats[0 * 128 + j], S2 = g_stats[1 * 128 + j];
    float Q1 = g_stats[2 * 128 + j], Q2 = g_stats[3 * 128 + j];
    float CX = g_stats[4 * 128 + j];
    float S3 = g_stats[5 * 128 + j], Q3 = g_stats[6 * 128 + j];

    float invMP = 1.0f / (float)MP;
    float mu = (b1 * S1 + b2 * S2) * invMP;
    float ex2 = (b1 * b1 * Q1 + 2.f * b1 * b2 * CX + b2 * b2 * Q2) * invMP;
    float var = ex2 - mu * mu;
    float sc = gamma[j] * rsqrtf(var + 1e-5f);
    g_scale_p[j] = sc;
    g_shift_p[j] = betaBN[j] - mu * sc;

    float invMA = 1.0f / (float)MA;
    float mua = S3 * invMA;
    float vara = Q3 * invMA - mua * mua;
    float sca = gamma[j] * rsqrtf(vara + 1e-5f);
    g_scale_a[j] = sca;
    g_shift_a[j] = betaBN[j] - mua * sca;
}

// -------- combine + BN + row L2 normalize (merged: y=0 paper, y=1 author) ----
__global__ __launch_bounds__(256) void out_kernel(
    const float* __restrict__ z1, const float* __restrict__ z2,
    const float* __restrict__ z3, float* __restrict__ out, int MP, int MA) {
    int gt = blockIdx.x * blockDim.x + threadIdx.x;
    int row = gt >> 5, lane = gt & 31;
    float4 y;
    float* o;
    if (blockIdx.y == 0) {
        if (row >= MP) return;
        float b1 = g_beta[0], b2 = g_beta[1];
        float4 v1 = *((const float4*)(z1 + (size_t)row * 128) + lane);
        float4 v2 = *((const float4*)(z2 + (size_t)row * 128) + lane);
        float4 sc = *(const float4*)&g_scale_p[lane * 4];
        float4 sh = *(const float4*)&g_shift_p[lane * 4];
        y.x = (b1 * v1.x + b2 * v2.x) * sc.x + sh.x;
        y.y = (b1 * v1.y + b2 * v2.y) * sc.y + sh.y;
        y.z = (b1 * v1.z + b2 * v2.z) * sc.z + sh.z;
        y.w = (b1 * v1.w + b2 * v2.w) * sc.w + sh.w;
        o = out + (size_t)row * 128;
    } else {
        if (row >= MA) return;
        float4 v = *((const float4*)(z3 + (size_t)row * 128) + lane);
        float4 sc = *(const float4*)&g_scale_a[lane * 4];
        float4 sh = *(const float4*)&g_shift_a[lane * 4];
        y.x = v.x * sc.x + sh.x;
        y.y = v.y * sc.y + sh.y;
        y.z = v.z * sc.z + sh.z;
        y.w = v.w * sc.w + sh.w;
        o = out + (size_t)(MP + row) * 128;
    }
    float ss = y.x * y.x + y.y * y.y + y.z * y.z + y.w * y.w;
#pragma unroll
    for (int off = 16; off > 0; off >>= 1) ss += __shfl_xor_sync(0xffffffffu, ss, off);
    float inv = rsqrtf(ss + 1e-12f);
    ((float4*)o)[lane] = make_float4(y.x * inv, y.y * inv, y.z * inv, y.w * inv);
}

// ---------------- launch ----------------
extern "C" void kernel_launch(void* const* d_in, const int* in_sizes, int n_in,
                              void* d_out, int out_size) {
    const float* h_paper  = (const float*)d_in[0];
    const float* h_author = (const float*)d_in[1];
    const float* W1   = (const float*)d_in[2];
    const float* W2   = (const float*)d_in[3];
    const float* W3   = (const float*)d_in[4];
    const float* attW = (const float*)d_in[5];
    const float* attb = (const float*)d_in[6];
    const float* attq = (const float*)d_in[7];
    const float* gamma  = (const float*)d_in[8];
    const float* betaBN = (const float*)d_in[9];
    const int* s1 = (const int*)d_in[10];
    const int* d1 = (const int*)d_in[11];
    const int* s2 = (const int*)d_in[12];
    const int* d2 = (const int*)d_in[13];
    const int* s3 = (const int*)d_in[14];
    const int* d3 = (const int*)d_in[15];
    float* out = (float*)d_out;

    const int MP = in_sizes[0] / Dv;
    const int MA = in_sizes[1] / Dv;
    const int E  = in_sizes[10];

    float *agg1, *agg2, *agg3, *z1, *z2, *z3, *deg, *wsum;
    cudaGetSymbolAddress((void**)&agg1, g_agg1);
    cudaGetSymbolAddress((void**)&agg2, g_agg2);
    cudaGetSymbolAddress((void**)&agg3, g_agg3);
    cudaGetSymbolAddress((void**)&z1, g_z1);
    cudaGetSymbolAddress((void**)&z2, g_z2);
    cudaGetSymbolAddress((void**)&z3, g_z3);
    cudaGetSymbolAddress((void**)&deg, g_deg);
    cudaGetSymbolAddress((void**)&wsum, g_wsum);

    // 1. zero deg/stats/wsum
    zero_kernel<<<(6 * 50000 / 4 + 255) / 256, 256>>>();
    // 2. fp16 feature table
    {
        size_t n8 = (size_t)(MP + MA) * Dv / 8;
        h2half_kernel<<<(int)((n8 + 255) / 256), 256>>>(h_paper, h_author);
    }
    // 3. degrees (raw counts)
    degree_kernel<<<(E + 255) / 256, 256>>>(s1, d1, s2, d2, s3, d3, E);
    // 4. CSR build: 3-phase chunked scan + fill
    {
        int nb = (MP + 255) / 256;   // == 196
        dim3 g1(nb, 3);
        prefix1_kernel<<<g1, 256>>>(MP);
        prefix2_kernel<<<3, 256>>>(nb);
        prefix3_kernel<<<g1, 256>>>(MP);
        dim3 gf((E + 255) / 256, 3);
        fill_kernel<<<gf, 256>>>(s1, d1, s2, d2, s3, d3, E);
    }
    // 5. scatter: warp per dst row, 8-edge chunks
    {
        dim3 g((MP * 32 + 255) / 256, 3);
        scatter_kernel<<<g, 256>>>(MP);
    }
    // 6. conv GEMMs + attention GEMMs (fp16 m16n8k16, double-buffered)
    {
        dim3 g((MP + 127) / 128, 3);
        conv_gemm_f16<<<g, 256>>>(agg1, agg2, agg3, W1, W2, W3,
                                  deg + 1 * 50000, deg + 3 * 50000, deg + 5 * 50000,
                                  z1, z2, z3, MP);
        dim3 ga((MP + 127) / 128, 2);
        att_gemm_f16<<<ga, 256>>>(z1, z2, attW, attb, attq, wsum, MP);
    }
    // 7. moments, finalize, outputs
    {
        dim3 gs((MP + 127) / 128, 2);
        stats_kernel<<<gs, 128>>>(z1, z2, z3, MP, MA);
    }
    finalize_kernel<<<1, 128>>>(gamma, betaBN, MP, MA);
    {
        dim3 go((MP * 32 + 255) / 256, 2);
        out_kernel<<<go, 256>>>(z1, z2, z3, out, MP, MA);
    }
}

// round 16
// speedup vs baseline: 1.0051x; 1.0051x over previous
#include <cuda_runtime.h>
#include <cuda_fp16.h>
#include <cstdint>

#define NPv 50000
#define NAv 50000
#define Dv  128
#define Emax 800000
#define NCHUNK 196   // ceil(50000/256)

// ---------------- scratch ----------------
__device__ float g_agg1[(size_t)NPv * Dv];
__device__ float g_agg2[(size_t)NPv * Dv];
__device__ float g_agg3[(size_t)NAv * Dv];
__device__ float g_z1[(size_t)NPv * Dv];
__device__ float g_z2[(size_t)NPv * Dv];
__device__ float g_z3[(size_t)NAv * Dv];
__device__ __half g_h16[(size_t)(NPv + NAv) * Dv];   // [paper | author] fp16 table
__device__ float g_deg[6 * 50000];                   // RAW counts
__device__ float g_stats[7 * 128];
__device__ float g_wsum[2];
__device__ float g_beta[2];
__device__ float g_scale_p[128], g_shift_p[128];
__device__ float g_scale_a[128], g_shift_a[128];
__device__ int   g_ebuf[3][Emax];                    // dst-sorted src ids (CSR)
__device__ int   g_soffs[3][50000];                  // post-fill: segment END offsets
__device__ int   g_csum[3][NCHUNK];

// ---------------- fp16 mma helper ----------------
__device__ __forceinline__ void mma_f16(float4& d, const uint32_t a[4],
                                        uint32_t b0, uint32_t b1) {
    asm volatile(
        "mma.sync.aligned.m16n8k16.row.col.f32.f16.f16.f32 "
        "{%0,%1,%2,%3},{%4,%5,%6,%7},{%8,%9},{%0,%1,%2,%3};"
        : "+f"(d.x), "+f"(d.y), "+f"(d.z), "+f"(d.w)
        : "r"(a[0]), "r"(a[1]), "r"(a[2]), "r"(a[3]), "r"(b0), "r"(b1));
}
__device__ __forceinline__ uint32_t h2bits(__half2 h) {
    return *(uint32_t*)&h;
}

// ---------------- zero scratch (deg/stats/wsum only) ----------------
__global__ void zero_kernel() {
    int i = blockIdx.x * blockDim.x + threadIdx.x;
    float4 z = make_float4(0.f, 0.f, 0.f, 0.f);
    if (i < (6 * 50000) / 4) ((float4*)g_deg)[i] = z;
    if (i < (7 * 128) / 4) ((float4*)g_stats)[i] = z;
    if (i < 2) g_wsum[i] = 0.f;
}

// ---------------- fp32 -> fp16 feature table ----------------
__global__ void h2half_kernel(const float* __restrict__ hp, const float* __restrict__ ha) {
    size_t i = (size_t)blockIdx.x * blockDim.x + threadIdx.x;   // unit = 8 elems
    const size_t n8 = (size_t)NPv * Dv / 8;
    const float* srcB;
    size_t j;
    if (i < n8) { srcB = hp; j = i; }
    else if (i < 2 * n8) { srcB = ha; j = i - n8; }
    else return;
    float4 a = ((const float4*)srcB)[2 * j];
    float4 b = ((const float4*)srcB)[2 * j + 1];
    __half2 p0 = __floats2half2_rn(a.x, a.y);
    __half2 p1 = __floats2half2_rn(a.z, a.w);
    __half2 p2 = __floats2half2_rn(b.x, b.y);
    __half2 p3 = __floats2half2_rn(b.z, b.w);
    uint4 o;
    o.x = h2bits(p0); o.y = h2bits(p1);
    o.z = h2bits(p2); o.w = h2bits(p3);
    ((uint4*)g_h16)[i] = o;
}

// ---------------- degrees (raw counts) ----------------
__global__ void degree_kernel(const int* __restrict__ s1, const int* __restrict__ d1,
                              const int* __restrict__ s2, const int* __restrict__ d2,
                              const int* __restrict__ s3, const int* __restrict__ d3,
                              int nE) {
    int i = blockIdx.x * blockDim.x + threadIdx.x;
    if (i >= nE) return;
    atomicAdd(&g_deg[0 * 50000 + s1[i]], 1.0f);
    atomicAdd(&g_deg[1 * 50000 + d1[i]], 1.0f);
    atomicAdd(&g_deg[2 * 50000 + s2[i]], 1.0f);
    atomicAdd(&g_deg[3 * 50000 + d2[i]], 1.0f);
    atomicAdd(&g_deg[4 * 50000 + s3[i]], 1.0f);
    atomicAdd(&g_deg[5 * 50000 + d3[i]], 1.0f);
}

// -------- chunked exclusive scan of deg_in (3 phases) ------------------------
__global__ __launch_bounds__(256) void prefix1_kernel(int M) {
    int r = blockIdx.y, b = blockIdx.x, t = threadIdx.x;
    int n = b * 256 + t;
    int iv = 0;
    if (n < M) iv = (int)(g_deg[(2 * r + 1) * 50000 + n] + 0.5f);
    __shared__ int sh[256];
    sh[t] = iv;
    __syncthreads();
#pragma unroll
    for (int o = 128; o > 0; o >>= 1) {
        if (t < o) sh[t] += sh[t + o];
        __syncthreads();
    }
    if (t == 0) g_csum[r][b] = sh[0];
}

__global__ __launch_bounds__(256) void prefix2_kernel(int nb) {
    int r = blockIdx.x, t = threadIdx.x;
    __shared__ int sh[256];
    int v = (t < nb) ? g_csum[r][t] : 0;
    sh[t] = v;
    __syncthreads();
#pragma unroll
    for (int o = 1; o < 256; o <<= 1) {
        int u = (t >= o) ? sh[t - o] : 0;
        __syncthreads();
        sh[t] += u;
        __syncthreads();
    }
    if (t < nb) g_csum[r][t] = sh[t] - v;   // exclusive
}

__global__ __launch_bounds__(256) void prefix3_kernel(int M) {
    int r = blockIdx.y, b = blockIdx.x, t = threadIdx.x;
    int n = b * 256 + t;
    int iv = 0;
    if (n < M) iv = (int)(g_deg[(2 * r + 1) * 50000 + n] + 0.5f);
    __shared__ int sh[256];
    sh[t] = iv;
    __syncthreads();
#pragma unroll
    for (int o = 1; o < 256; o <<= 1) {
        int u = (t >= o) ? sh[t - o] : 0;
        __syncthreads();
        sh[t] += u;
        __syncthreads();
    }
    if (n < M) g_soffs[r][n] = sh[t] - iv + g_csum[r][b];
}

// ---------------- fill: dst-grouped src lists (CSR) ----------------
__global__ void fill_kernel(const int* __restrict__ s1, const int* __restrict__ d1,
                            const int* __restrict__ s2, const int* __restrict__ d2,
                            const int* __restrict__ s3, const int* __restrict__ d3,
                            int nE) {
    int r = blockIdx.y;
    const int* src = r == 0 ? s1 : r == 1 ? s2 : s3;
    const int* dst = r == 0 ? d1 : r == 1 ? d2 : d3;
    int i = blockIdx.x * blockDim.x + threadIdx.x;
    if (i >= nE) return;
    int sV = src[i], dV = dst[i];
    int pos = atomicAdd(&g_soffs[r][dV], 1);
    g_ebuf[r][pos] = sV;
}
// After fill: g_soffs[r][d] == END offset of dst d's segment.

// --- scatter: warp per dst row, 8-edge chunks (MLP=8), single STG.128 --------
__global__ __launch_bounds__(256) void scatter_kernel(int M) {
    int rel = blockIdx.y;
    const int* eb = g_ebuf[rel];
    const __half* H = (rel == 1) ? g_h16 : g_h16 + (size_t)NPv * Dv;
    const float* degout = g_deg + (2 * rel) * 50000;         // raw out-degree
    const float* degin = g_deg + (2 * rel + 1) * 50000;      // raw in-degree
    float* agg = (rel == 0) ? g_agg1 : (rel == 1) ? g_agg2 : g_agg3;

    int dst = (blockIdx.x * blockDim.x + threadIdx.x) >> 5;
    int lane = threadIdx.x & 31;
    if (dst >= M) return;

    int end = __ldg(&g_soffs[rel][dst]);
    int deg = (int)(__ldg(degin + dst) + 0.5f);
    int start = end - deg;

    float4 acc = make_float4(0.f, 0.f, 0.f, 0.f);
    for (int e = start; e < end; e += 8) {
        int m = min(8, end - e);
        int s[8];
#pragma unroll
        for (int i = 0; i < 8; i++) s[i] = __ldg(eb + min(e + i, end - 1));
        float sc[8];
#pragma unroll
        for (int i = 0; i < 8; i++) sc[i] = rsqrtf(fmaxf(__ldg(degout + s[i]), 1.0f));
        uint2 raw[8];
#pragma unroll
        for (int i = 0; i < 8; i++)
            raw[i] = *((const uint2*)(H + (size_t)s[i] * Dv) + lane);   // MLP=8
#pragma unroll
        for (int i = 0; i < 8; i++) {
            if (i < m) {
                float2 f01 = __half22float2(*(const __half2*)&raw[i].x);
                float2 f23 = __half22float2(*(const __half2*)&raw[i].y);
                float c = sc[i];
                acc.x += f01.x * c;
                acc.y += f01.y * c;
                acc.z += f23.x * c;
                acc.w += f23.y * c;
            }
        }
    }
    *((float4*)(agg + (size_t)dst * Dv) + lane) = acc;   // one plain store
}

// ============ FP16 GEMM core: block tile 128x128, m16n8k16, fp32 accum =======
// (single-buffered: the R14 reference version)
#define GEMM_PROLOGUE()                                                        \
    __shared__ __half As[128][40];                                             \
    __shared__ __half2 Ws2[16][136];                                           \
    const int tid = threadIdx.x;                                               \
    const int wid = tid >> 5, lane = tid & 31;                                 \
    const int grp = lane >> 2, tig = lane & 3;                                 \
    const int rowBase = blockIdx.x * 128;                                      \
    const int rowOff = (wid & 3) * 32;                                         \
    const int colOff = (wid >> 2) * 64;                                        \
    float4 acc[2][8];                                                          \
    _Pragma("unroll") for (int ms = 0; ms < 2; ms++)                           \
        _Pragma("unroll") for (int ns = 0; ns < 8; ns++)                       \
            acc[ms][ns] = make_float4(0.f, 0.f, 0.f, 0.f);

#define LOAD_CHUNK(kc)                                                         \
    _Pragma("unroll") for (int j = 0; j < 4; j++) {                            \
        int i = tid + 256 * j;                                                 \
        int r = i >> 3, c4 = (i & 7) << 2;                                     \
        int gr = min(rowBase + r, M - 1);                                      \
        aPre[j] = *(const float4*)(A + (size_t)gr * 128 + (kc) * 32 + c4);     \
    }                                                                          \
    _Pragma("unroll") for (int jj = 0; jj < 2; jj++) {                         \
        int u = tid + 256 * jj;                                                \
        int k2 = u >> 5, n4 = (u & 31) << 2;                                   \
        wA[jj] = *(const float4*)(W + (size_t)((kc) * 32 + 2 * k2) * 128 + n4);     \
        wB[jj] = *(const float4*)(W + (size_t)((kc) * 32 + 2 * k2 + 1) * 128 + n4); \
    }

#define STORE_CHUNK()                                                          \
    _Pragma("unroll") for (int j = 0; j < 4; j++) {                            \
        int i = tid + 256 * j;                                                 \
        int r = i >> 3, c4 = (i & 7) << 2;                                     \
        uint2 ta;                                                              \
        ta.x = h2bits(__floats2half2_rn(aPre[j].x, aPre[j].y));                \
        ta.y = h2bits(__floats2half2_rn(aPre[j].z, aPre[j].w));                \
        *(uint2*)&As[r][c4] = ta;                                              \
    }                                                                          \
    _Pragma("unroll") for (int jj = 0; jj < 2; jj++) {                         \
        int u = tid + 256 * jj;                                                \
        int k2 = u >> 5, n4 = (u & 31) << 2;                                   \
        uint4 tw;                                                              \
        tw.x = h2bits(__halves2half2(__float2half_rn(wA[jj].x), __float2half_rn(wB[jj].x))); \
        tw.y = h2bits(__halves2half2(__float2half_rn(wA[jj].y), __float2half_rn(wB[jj].y))); \
        tw.z = h2bits(__halves2half2(__float2half_rn(wA[jj].z), __float2half_rn(wB[jj].z))); \
        tw.w = h2bits(__halves2half2(__float2half_rn(wA[jj].w), __float2half_rn(wB[jj].w))); \
        *(uint4*)&Ws2[k2][n4] = tw;                                            \
    }

#define MMA_CHUNK()                                                            \
    _Pragma("unroll") for (int ks = 0; ks < 2; ks++) {                         \
        int k0 = ks * 16;                                                      \
        uint32_t a[2][4];                                                      \
        _Pragma("unroll") for (int ms = 0; ms < 2; ms++) {                     \
            int r = rowOff + ms * 16 + grp;                                    \
            a[ms][0] = *(const uint32_t*)&As[r][k0 + 2 * tig];                 \
            a[ms][1] = *(const uint32_t*)&As[r + 8][k0 + 2 * tig];             \
            a[ms][2] = *(const uint32_t*)&As[r][k0 + 8 + 2 * tig];             \
            a[ms][3] = *(const uint32_t*)&As[r + 8][k0 + 8 + 2 * tig];         \
        }                                                                      \
        _Pragma("unroll") for (int ns = 0; ns < 8; ns++) {                     \
            int cn = colOff + ns * 8 + grp;                                    \
            uint32_t b0 = h2bits(Ws2[ks * 8 + tig][cn]);                       \
            uint32_t b1 = h2bits(Ws2[ks * 8 + 4 + tig][cn]);                   \
            mma_f16(acc[0][ns], a[0], b0, b1);                                 \
            mma_f16(acc[1][ns], a[1], b0, b1);                                 \
        }                                                                      \
    }

#define GEMM_MAINLOOP()                                                        \
    float4 aPre[4], wA[2], wB[2];                                              \
    LOAD_CHUNK(0)                                                              \
    _Pragma("unroll") for (int kc = 0; kc < 4; kc++) {                         \
        if (kc > 0) __syncthreads();                                           \
        STORE_CHUNK()                                                          \
        __syncthreads();                                                       \
        if (kc < 3) { LOAD_CHUNK(kc + 1) }                                     \
        MMA_CHUNK()                                                            \
    }

// conv GEMM: C = (A @ W) * rsqrt(max(deg_in,1)); blockIdx.y = relation
__global__ __launch_bounds__(256, 2) void conv_gemm_f16(
    const float* __restrict__ A1, const float* __restrict__ A2, const float* __restrict__ A3,
    const float* __restrict__ W1, const float* __restrict__ W2, const float* __restrict__ W3,
    const float* __restrict__ rs1, const float* __restrict__ rs2, const float* __restrict__ rs3,
    float* __restrict__ C1, float* __restrict__ C2, float* __restrict__ C3, int M) {
    const int rel = blockIdx.y;
    const float* A = rel == 0 ? A1 : rel == 1 ? A2 : A3;
    const float* W = rel == 0 ? W1 : rel == 1 ? W2 : W3;
    const float* rs = rel == 0 ? rs1 : rel == 1 ? rs2 : rs3;   // raw deg_in
    float* C = rel == 0 ? C1 : rel == 1 ? C2 : C3;

    GEMM_PROLOGUE()
    GEMM_MAINLOOP()

#pragma unroll
    for (int ms = 0; ms < 2; ms++) {
        int rA = rowBase + rowOff + ms * 16 + grp;
        int rB = rA + 8;
        float sA = (rA < M) ? rsqrtf(fmaxf(rs[rA], 1.0f)) : 0.f;
        float sB = (rB < M) ? rsqrtf(fmaxf(rs[rB], 1.0f)) : 0.f;
#pragma unroll
        for (int ns = 0; ns < 8; ns++) {
            int cC = colOff + ns * 8 + 2 * tig;
            if (rA < M) {
                float2 o = make_float2(acc[ms][ns].x * sA, acc[ms][ns].y * sA);
                *(float2*)(C + (size_t)rA * 128 + cC) = o;
            }
            if (rB < M) {
                float2 o = make_float2(acc[ms][ns].z * sB, acc[ms][ns].w * sB);
                *(float2*)(C + (size_t)rB * 128 + cC) = o;
            }
        }
    }
}

__global__ __launch_bounds__(256, 2) void att_gemm_f16(
    const float* __restrict__ Z1, const float* __restrict__ Z2,
    const float* __restrict__ W,
    const float* __restrict__ bb, const float* __restrict__ qq,
    float* __restrict__ wsum, int M) {
    const float* A = blockIdx.y == 0 ? Z1 : Z2;

    GEMM_PROLOGUE()
    GEMM_MAINLOOP()

    float p = 0.f;
#pragma unroll
    for (int ms = 0; ms < 2; ms++) {
        int rA = rowBase + rowOff + ms * 16 + grp;
        int rB = rA + 8;
#pragma unroll
        for (int ns = 0; ns < 8; ns++) {
            int cC = colOff + ns * 8 + 2 * tig;
            float b0v = __ldg(bb + cC), b1v = __ldg(bb + cC + 1);
            float q0v = __ldg(qq + cC), q1v = __ldg(qq + cC + 1);
            if (rA < M)
                p += tanhf(acc[ms][ns].x + b0v) * q0v + tanhf(acc[ms][ns].y + b1v) * q1v;
            if (rB < M)
                p += tanhf(acc[ms][ns].z + b0v) * q0v + tanhf(acc[ms][ns].w + b1v) * q1v;
        }
    }
#pragma unroll
    for (int o = 16; o > 0; o >>= 1) p += __shfl_xor_sync(0xffffffffu, p, o);
    if (lane == 0) atomicAdd(wsum + blockIdx.y, p);
}

// ---------------- column moments (merged: y=0 paper, y=1 author) -------------
__global__ __launch_bounds__(128) void stats_kernel(
    const float* __restrict__ z1, const float* __restrict__ z2,
    const float* __restrict__ z3, int MP, int MA) {
    int c = threadIdx.x;
    if (blockIdx.y == 0) {
        int r0 = blockIdx.x * 128;
        int r1 = min(r0 + 128, MP);
        if (r0 >= MP) return;
        float s1 = 0.f, s2 = 0.f, q1 = 0.f, q2 = 0.f, cx = 0.f;
        for (int r = r0; r < r1; r++) {
            float v1 = z1[(size_t)r * 128 + c];
            float v2 = z2[(size_t)r * 128 + c];
            s1 += v1; s2 += v2; q1 += v1 * v1; q2 += v2 * v2; cx += v1 * v2;
        }
        atomicAdd(&g_stats[0 * 128 + c], s1);
        atomicAdd(&g_stats[1 * 128 + c], s2);
        atomicAdd(&g_stats[2 * 128 + c], q1);
        atomicAdd(&g_stats[3 * 128 + c], q2);
        atomicAdd(&g_stats[4 * 128 + c], cx);
    } else {
        int r0 = blockIdx.x * 128;
        int r1 = min(r0 + 128, MA);
        if (r0 >= MA) return;
        float s3 = 0.f, q3 = 0.f;
        for (int r = r0; r < r1; r++) {
            float v = z3[(size_t)r * 128 + c];
            s3 += v; q3 += v * v;
        }
        atomicAdd(&g_stats[5 * 128 + c], s3);
        atomicAdd(&g_stats[6 * 128 + c], q3);
    }
}

// ---------------- finalize ----------------
__global__ void finalize_kernel(const float* __restrict__ gamma, const float* __restrict__ betaBN,
                                int MP, int MA) {
    int j = threadIdx.x;
    float w1 = g_wsum[0] / (float)MP;
    float w2 = g_wsum[1] / (float)MP;
    float m = fmaxf(w1, w2);
    float e1 = expf(w1 - m), e2 = expf(w2 - m);
    float b1 = e1 / (e1 + e2), b2 = e2 / (e1 + e2);
    if (j == 0) { g_beta[0] = b1; g_beta[1] = b2; }

    float S1 = g_stats[0 * 128 + j], S2 = g_stats[1 * 128 + j];
    float Q1 = g_stats[2 * 128 + j], Q2 = g_stats[3 * 128 + j];
    float CX = g_stats[4 * 128 + j];
    float S3 = g_stats[5 * 128 + j], Q3 = g_stats[6 * 128 + j];

    float invMP = 1.0f / (float)MP;
    float mu = (b1 * S1 + b2 * S2) * invMP;
    float ex2 = (b1 * b1 * Q1 + 2.f * b1 * b2 * CX + b2 * b2 * Q2) * invMP;
    float var = ex2 - mu * mu;
    float sc = gamma[j] * rsqrtf(var + 1e-5f);
    g_scale_p[j] = sc;
    g_shift_p[j] = betaBN[j] - mu * sc;

    float invMA = 1.0f / (float)MA;
    float mua = S3 * invMA;
    float vara = Q3 * invMA - mua * mua;
    float sca = gamma[j] * rsqrtf(vara + 1e-5f);
    g_scale_a[j] = sca;
    g_shift_a[j] = betaBN[j] - mua * sca;
}

// -------- combine + BN + row L2 normalize (merged: y=0 paper, y=1 author) ----
__global__ __launch_bounds__(256) void out_kernel(
    const float* __restrict__ z1, const float* __restrict__ z2,
    const float* __restrict__ z3, float* __restrict__ out, int MP, int MA) {
    int gt = blockIdx.x * blockDim.x + threadIdx.x;
    int row = gt >> 5, lane = gt & 31;
    float4 y;
    float* o;
    if (blockIdx.y == 0) {
        if (row >= MP) return;
        float b1 = g_beta[0], b2 = g_beta[1];
        float4 v1 = *((const float4*)(z1 + (size_t)row * 128) + lane);
        float4 v2 = *((const float4*)(z2 + (size_t)row * 128) + lane);
        float4 sc = *(const float4*)&g_scale_p[lane * 4];
        float4 sh = *(const float4*)&g_shift_p[lane * 4];
        y.x = (b1 * v1.x + b2 * v2.x) * sc.x + sh.x;
        y.y = (b1 * v1.y + b2 * v2.y) * sc.y + sh.y;
        y.z = (b1 * v1.z + b2 * v2.z) * sc.z + sh.z;
        y.w = (b1 * v1.w + b2 * v2.w) * sc.w + sh.w;
        o = out + (size_t)row * 128;
    } else {
        if (row >= MA) return;
        float4 v = *((const float4*)(z3 + (size_t)row * 128) + lane);
        float4 sc = *(const float4*)&g_scale_a[lane * 4];
        float4 sh = *(const float4*)&g_shift_a[lane * 4];
        y.x = v.x * sc.x + sh.x;
        y.y = v.y * sc.y + sh.y;
        y.z = v.z * sc.z + sh.z;
        y.w = v.w * sc.w + sh.w;
        o = out + (size_t)(MP + row) * 128;
    }
    float ss = y.x * y.x + y.y * y.y + y.z * y.z + y.w * y.w;
#pragma unroll
    for (int off = 16; off > 0; off >>= 1) ss += __shfl_xor_sync(0xffffffffu, ss, off);
    float inv = rsqrtf(ss + 1e-12f);
    ((float4*)o)[lane] = make_float4(y.x * inv, y.y * inv, y.z * inv, y.w * inv);
}

// ---------------- launch ----------------
extern "C" void kernel_launch(void* const* d_in, const int* in_sizes, int n_in,
                              void* d_out, int out_size) {
    const float* h_paper  = (const float*)d_in[0];
    const float* h_author = (const float*)d_in[1];
    const float* W1   = (const float*)d_in[2];
    const float* W2   = (const float*)d_in[3];
    const float* W3   = (const float*)d_in[4];
    const float* attW = (const float*)d_in[5];
    const float* attb = (const float*)d_in[6];
    const float* attq = (const float*)d_in[7];
    const float* gamma  = (const float*)d_in[8];
    const float* betaBN = (const float*)d_in[9];
    const int* s1 = (const int*)d_in[10];
    const int* d1 = (const int*)d_in[11];
    const int* s2 = (const int*)d_in[12];
    const int* d2 = (const int*)d_in[13];
    const int* s3 = (const int*)d_in[14];
    const int* d3 = (const int*)d_in[15];
    float* out = (float*)d_out;

    const int MP = in_sizes[0] / Dv;
    const int MA = in_sizes[1] / Dv;
    const int E  = in_sizes[10];

    float *agg1, *agg2, *agg3, *z1, *z2, *z3, *deg, *wsum;
    cudaGetSymbolAddress((void**)&agg1, g_agg1);
    cudaGetSymbolAddress((void**)&agg2, g_agg2);
    cudaGetSymbolAddress((void**)&agg3, g_agg3);
    cudaGetSymbolAddress((void**)&z1, g_z1);
    cudaGetSymbolAddress((void**)&z2, g_z2);
    cudaGetSymbolAddress((void**)&z3, g_z3);
    cudaGetSymbolAddress((void**)&deg, g_deg);
    cudaGetSymbolAddress((void**)&wsum, g_wsum);

    // 1. zero deg/stats/wsum
    zero_kernel<<<(6 * 50000 / 4 + 255) / 256, 256>>>();
    // 2. fp16 feature table
    {
        size_t n8 = (size_t)(MP + MA) * Dv / 8;
        h2half_kernel<<<(int)((n8 + 255) / 256), 256>>>(h_paper, h_author);
    }
    // 3. degrees (raw counts)
    degree_kernel<<<(E + 255) / 256, 256>>>(s1, d1, s2, d2, s3, d3, E);
    // 4. CSR build: 3-phase chunked scan + fill
    {
        int nb = (MP + 255) / 256;   // == 196
        dim3 g1(nb, 3);
        prefix1_kernel<<<g1, 256>>>(MP);
        prefix2_kernel<<<3, 256>>>(nb);
        prefix3_kernel<<<g1, 256>>>(MP);
        dim3 gf((E + 255) / 256, 3);
        fill_kernel<<<gf, 256>>>(s1, d1, s2, d2, s3, d3, E);
    }
    // 5. scatter: warp per dst row, 8-edge chunks
    {
        dim3 g((MP * 32 + 255) / 256, 3);
        scatter_kernel<<<g, 256>>>(MP);
    }
    // 6. conv GEMMs + attention GEMMs (fp16 m16n8k16, single-buffered R14 core)
    {
        dim3 g((MP + 127) / 128, 3);
        conv_gemm_f16<<<g, 256>>>(agg1, agg2, agg3, W1, W2, W3,
                                  deg + 1 * 50000, deg + 3 * 50000, deg + 5 * 50000,
                                  z1, z2, z3, MP);
        dim3 ga((MP + 127) / 128, 2);
        att_gemm_f16<<<ga, 256>>>(z1, z2, attW, attb, attq, wsum, MP);
    }
    // 7. moments, finalize, outputs
    {
        dim3 gs((MP + 127) / 128, 2);
        stats_kernel<<<gs, 128>>>(z1, z2, z3, MP, MA);
    }
    finalize_kernel<<<1, 128>>>(gamma, betaBN, MP, MA);
    {
        dim3 go((MP * 32 + 255) / 256, 2);
        out_kernel<<<go, 256>>>(z1, z2, z3, out, MP, MA);
    }
}

// round 17
// speedup vs baseline: 1.0216x; 1.0164x over previous
#include <cuda_runtime.h>
#include <cuda_fp16.h>
#include <cstdint>

#define NPv 50000
#define NAv 50000
#define Dv  128
#define Emax 800000
#define NCHUNK 196   // ceil(50000/256)

// ---------------- scratch ----------------
__device__ float g_agg1[(size_t)NPv * Dv];
__device__ float g_agg2[(size_t)NPv * Dv];
__device__ float g_agg3[(size_t)NAv * Dv];
__device__ float g_z1[(size_t)NPv * Dv];
__device__ float g_z2[(size_t)NPv * Dv];
__device__ float g_z3[(size_t)NAv * Dv];
__device__ __half g_h16[(size_t)(NPv + NAv) * Dv];   // [paper | author] fp16 table
__device__ float g_deg[6 * 50000];                   // RAW counts
__device__ float g_stats[7 * 128];
__device__ float g_wsum[2];
__device__ float g_beta[2];
__device__ float g_scale_p[128], g_shift_p[128];
__device__ float g_scale_a[128], g_shift_a[128];
__device__ int   g_ebuf[3][Emax];                    // dst-sorted src ids (CSR)
__device__ int   g_soffs[3][50000];                  // post-fill: segment END offsets
__device__ int   g_csum[3][NCHUNK];

// ---------------- fp16 mma helper ----------------
__device__ __forceinline__ void mma_f16(float4& d, const uint32_t a[4],
                                        uint32_t b0, uint32_t b1) {
    asm volatile(
        "mma.sync.aligned.m16n8k16.row.col.f32.f16.f16.f32 "
        "{%0,%1,%2,%3},{%4,%5,%6,%7},{%8,%9},{%0,%1,%2,%3};"
        : "+f"(d.x), "+f"(d.y), "+f"(d.z), "+f"(d.w)
        : "r"(a[0]), "r"(a[1]), "r"(a[2]), "r"(a[3]), "r"(b0), "r"(b1));
}
__device__ __forceinline__ uint32_t h2bits(__half2 h) {
    return *(uint32_t*)&h;
}

// ------- init: zero deg/stats/wsum AND build fp16 feature table (merged) -----
__global__ void init_kernel(const float* __restrict__ hp, const float* __restrict__ ha) {
    size_t i = (size_t)blockIdx.x * blockDim.x + threadIdx.x;
    // part 1: fp16 table, unit = 8 elems
    const size_t n8 = (size_t)NPv * Dv / 8;
    if (i < 2 * n8) {
        const float* srcB;
        size_t j;
        if (i < n8) { srcB = hp; j = i; }
        else { srcB = ha; j = i - n8; }
        float4 a = ((const float4*)srcB)[2 * j];
        float4 b = ((const float4*)srcB)[2 * j + 1];
        __half2 p0 = __floats2half2_rn(a.x, a.y);
        __half2 p1 = __floats2half2_rn(a.z, a.w);
        __half2 p2 = __floats2half2_rn(b.x, b.y);
        __half2 p3 = __floats2half2_rn(b.z, b.w);
        uint4 o;
        o.x = h2bits(p0); o.y = h2bits(p1);
        o.z = h2bits(p2); o.w = h2bits(p3);
        ((uint4*)g_h16)[i] = o;
    }
    // part 2: zero scratch
    float4 z = make_float4(0.f, 0.f, 0.f, 0.f);
    if (i < (6 * 50000) / 4) ((float4*)g_deg)[i] = z;
    if (i < (7 * 128) / 4) ((float4*)g_stats)[i] = z;
    if (i < 2) g_wsum[i] = 0.f;
}

// ---------------- degrees (raw counts) ----------------
__global__ void degree_kernel(const int* __restrict__ s1, const int* __restrict__ d1,
                              const int* __restrict__ s2, const int* __restrict__ d2,
                              const int* __restrict__ s3, const int* __restrict__ d3,
                              int nE) {
    int i = blockIdx.x * blockDim.x + threadIdx.x;
    if (i >= nE) return;
    atomicAdd(&g_deg[0 * 50000 + s1[i]], 1.0f);
    atomicAdd(&g_deg[1 * 50000 + d1[i]], 1.0f);
    atomicAdd(&g_deg[2 * 50000 + s2[i]], 1.0f);
    atomicAdd(&g_deg[3 * 50000 + d2[i]], 1.0f);
    atomicAdd(&g_deg[4 * 50000 + s3[i]], 1.0f);
    atomicAdd(&g_deg[5 * 50000 + d3[i]], 1.0f);
}

// -------- chunked exclusive scan of deg_in (3 phases) ------------------------
__global__ __launch_bounds__(256) void prefix1_kernel(int M) {
    int r = blockIdx.y, b = blockIdx.x, t = threadIdx.x;
    int n = b * 256 + t;
    int iv = 0;
    if (n < M) iv = (int)(g_deg[(2 * r + 1) * 50000 + n] + 0.5f);
    __shared__ int sh[256];
    sh[t] = iv;
    __syncthreads();
#pragma unroll
    for (int o = 128; o > 0; o >>= 1) {
        if (t < o) sh[t] += sh[t + o];
        __syncthreads();
    }
    if (t == 0) g_csum[r][b] = sh[0];
}

__global__ __launch_bounds__(256) void prefix2_kernel(int nb) {
    int r = blockIdx.x, t = threadIdx.x;
    __shared__ int sh[256];
    int v = (t < nb) ? g_csum[r][t] : 0;
    sh[t] = v;
    __syncthreads();
#pragma unroll
    for (int o = 1; o < 256; o <<= 1) {
        int u = (t >= o) ? sh[t - o] : 0;
        __syncthreads();
        sh[t] += u;
        __syncthreads();
    }
    if (t < nb) g_csum[r][t] = sh[t] - v;   // exclusive
}

__global__ __launch_bounds__(256) void prefix3_kernel(int M) {
    int r = blockIdx.y, b = blockIdx.x, t = threadIdx.x;
    int n = b * 256 + t;
    int iv = 0;
    if (n < M) iv = (int)(g_deg[(2 * r + 1) * 50000 + n] + 0.5f);
    __shared__ int sh[256];
    sh[t] = iv;
    __syncthreads();
#pragma unroll
    for (int o = 1; o < 256; o <<= 1) {
        int u = (t >= o) ? sh[t - o] : 0;
        __syncthreads();
        sh[t] += u;
        __syncthreads();
    }
    if (n < M) g_soffs[r][n] = sh[t] - iv + g_csum[r][b];
}

// ---------------- fill: dst-grouped src lists (CSR) ----------------
__global__ void fill_kernel(const int* __restrict__ s1, const int* __restrict__ d1,
                            const int* __restrict__ s2, const int* __restrict__ d2,
                            const int* __restrict__ s3, const int* __restrict__ d3,
                            int nE) {
    int r = blockIdx.y;
    const int* src = r == 0 ? s1 : r == 1 ? s2 : s3;
    const int* dst = r == 0 ? d1 : r == 1 ? d2 : d3;
    int i = blockIdx.x * blockDim.x + threadIdx.x;
    if (i >= nE) return;
    int sV = src[i], dV = dst[i];
    int pos = atomicAdd(&g_soffs[r][dV], 1);
    g_ebuf[r][pos] = sV;
}
// After fill: g_soffs[r][d] == END offset of dst d's segment.

// --- scatter: warp per dst row, 4-edge chunks (R14 reference), STG.128 -------
__global__ __launch_bounds__(256) void scatter_kernel(int M) {
    int rel = blockIdx.y;
    const int* eb = g_ebuf[rel];
    const __half* H = (rel == 1) ? g_h16 : g_h16 + (size_t)NPv * Dv;
    const float* degout = g_deg + (2 * rel) * 50000;         // raw out-degree
    const float* degin = g_deg + (2 * rel + 1) * 50000;      // raw in-degree
    float* agg = (rel == 0) ? g_agg1 : (rel == 1) ? g_agg2 : g_agg3;

    int dst = (blockIdx.x * blockDim.x + threadIdx.x) >> 5;
    int lane = threadIdx.x & 31;
    if (dst >= M) return;

    int end = __ldg(&g_soffs[rel][dst]);
    int deg = (int)(__ldg(degin + dst) + 0.5f);
    int start = end - deg;

    float4 acc = make_float4(0.f, 0.f, 0.f, 0.f);
    for (int e = start; e < end; e += 4) {
        int m = min(4, end - e);
        int s[4];
#pragma unroll
        for (int i = 0; i < 4; i++) s[i] = __ldg(eb + min(e + i, end - 1));
        float sc[4];
#pragma unroll
        for (int i = 0; i < 4; i++) sc[i] = rsqrtf(fmaxf(__ldg(degout + s[i]), 1.0f));
        uint2 raw[4];
#pragma unroll
        for (int i = 0; i < 4; i++)
            raw[i] = *((const uint2*)(H + (size_t)s[i] * Dv) + lane);   // MLP=4
#pragma unroll
        for (int i = 0; i < 4; i++) {
            if (i < m) {
                float2 f01 = __half22float2(*(const __half2*)&raw[i].x);
                float2 f23 = __half22float2(*(const __half2*)&raw[i].y);
                float c = sc[i];
                acc.x += f01.x * c;
                acc.y += f01.y * c;
                acc.z += f23.x * c;
                acc.w += f23.y * c;
            }
        }
    }
    *((float4*)(agg + (size_t)dst * Dv) + lane) = acc;   // one plain store
}

// ============ FP16 GEMM core: block tile 128x128, m16n8k16, fp32 accum =======
// (single-buffered: the R14 reference version)
#define GEMM_PROLOGUE()                                                        \
    __shared__ __half As[128][40];                                             \
    __shared__ __half2 Ws2[16][136];                                           \
    const int tid = threadIdx.x;                                               \
    const int wid = tid >> 5, lane = tid & 31;                                 \
    const int grp = lane >> 2, tig = lane & 3;                                 \
    const int rowBase = blockIdx.x * 128;                                      \
    const int rowOff = (wid & 3) * 32;                                         \
    const int colOff = (wid >> 2) * 64;                                        \
    float4 acc[2][8];                                                          \
    _Pragma("unroll") for (int ms = 0; ms < 2; ms++)                           \
        _Pragma("unroll") for (int ns = 0; ns < 8; ns++)                       \
            acc[ms][ns] = make_float4(0.f, 0.f, 0.f, 0.f);

#define LOAD_CHUNK(kc)                                                         \
    _Pragma("unroll") for (int j = 0; j < 4; j++) {                            \
        int i = tid + 256 * j;                                                 \
        int r = i >> 3, c4 = (i & 7) << 2;                                     \
        int gr = min(rowBase + r, M - 1);                                      \
        aPre[j] = *(const float4*)(A + (size_t)gr * 128 + (kc) * 32 + c4);     \
    }                                                                          \
    _Pragma("unroll") for (int jj = 0; jj < 2; jj++) {                         \
        int u = tid + 256 * jj;                                                \
        int k2 = u >> 5, n4 = (u & 31) << 2;                                   \
        wA[jj] = *(const float4*)(W + (size_t)((kc) * 32 + 2 * k2) * 128 + n4);     \
        wB[jj] = *(const float4*)(W + (size_t)((kc) * 32 + 2 * k2 + 1) * 128 + n4); \
    }

#define STORE_CHUNK()                                                          \
    _Pragma("unroll") for (int j = 0; j < 4; j++) {                            \
        int i = tid + 256 * j;                                                 \
        int r = i >> 3, c4 = (i & 7) << 2;                                     \
        uint2 ta;                                                              \
        ta.x = h2bits(__floats2half2_rn(aPre[j].x, aPre[j].y));                \
        ta.y = h2bits(__floats2half2_rn(aPre[j].z, aPre[j].w));                \
        *(uint2*)&As[r][c4] = ta;                                              \
    }                                                                          \
    _Pragma("unroll") for (int jj = 0; jj < 2; jj++) {                         \
        int u = tid + 256 * jj;                                                \
        int k2 = u >> 5, n4 = (u & 31) << 2;                                   \
        uint4 tw;                                                              \
        tw.x = h2bits(__halves2half2(__float2half_rn(wA[jj].x), __float2half_rn(wB[jj].x))); \
        tw.y = h2bits(__halves2half2(__float2half_rn(wA[jj].y), __float2half_rn(wB[jj].y))); \
        tw.z = h2bits(__halves2half2(__float2half_rn(wA[jj].z), __float2half_rn(wB[jj].z))); \
        tw.w = h2bits(__halves2half2(__float2half_rn(wA[jj].w), __float2half_rn(wB[jj].w))); \
        *(uint4*)&Ws2[k2][n4] = tw;                                            \
    }

#define MMA_CHUNK()                                                            \
    _Pragma("unroll") for (int ks = 0; ks < 2; ks++) {                         \
        int k0 = ks * 16;                                                      \
        uint32_t a[2][4];                                                      \
        _Pragma("unroll") for (int ms = 0; ms < 2; ms++) {                     \
            int r = rowOff + ms * 16 + grp;                                    \
            a[ms][0] = *(const uint32_t*)&As[r][k0 + 2 * tig];                 \
            a[ms][1] = *(const uint32_t*)&As[r + 8][k0 + 2 * tig];             \
            a[ms][2] = *(const uint32_t*)&As[r][k0 + 8 + 2 * tig];             \
            a[ms][3] = *(const uint32_t*)&As[r + 8][k0 + 8 + 2 * tig];         \
        }                                                                      \
        _Pragma("unroll") for (int ns = 0; ns < 8; ns++) {                     \
            int cn = colOff + ns * 8 + grp;                                    \
            uint32_t b0 = h2bits(Ws2[ks * 8 + tig][cn]);                       \
            uint32_t b1 = h2bits(Ws2[ks * 8 + 4 + tig][cn]);                   \
            mma_f16(acc[0][ns], a[0], b0, b1);                                 \
            mma_f16(acc[1][ns], a[1], b0, b1);                                 \
        }                                                                      \
    }

#define GEMM_MAINLOOP()                                                        \
    float4 aPre[4], wA[2], wB[2];                                              \
    LOAD_CHUNK(0)                                                              \
    _Pragma("unroll") for (int kc = 0; kc < 4; kc++) {                         \
        if (kc > 0) __syncthreads();                                           \
        STORE_CHUNK()                                                          \
        __syncthreads();                                                       \
        if (kc < 3) { LOAD_CHUNK(kc + 1) }                                     \
        MMA_CHUNK()                                                            \
    }

// conv GEMM: C = (A @ W) * rsqrt(max(deg_in,1)); blockIdx.y = relation
__global__ __launch_bounds__(256, 2) void conv_gemm_f16(
    const float* __restrict__ A1, const float* __restrict__ A2, const float* __restrict__ A3,
    const float* __restrict__ W1, const float* __restrict__ W2, const float* __restrict__ W3,
    const float* __restrict__ rs1, const float* __restrict__ rs2, const float* __restrict__ rs3,
    float* __restrict__ C1, float* __restrict__ C2, float* __restrict__ C3, int M) {
    const int rel = blockIdx.y;
    const float* A = rel == 0 ? A1 : rel == 1 ? A2 : A3;
    const float* W = rel == 0 ? W1 : rel == 1 ? W2 : W3;
    const float* rs = rel == 0 ? rs1 : rel == 1 ? rs2 : rs3;   // raw deg_in
    float* C = rel == 0 ? C1 : rel == 1 ? C2 : C3;

    GEMM_PROLOGUE()
    GEMM_MAINLOOP()

#pragma unroll
    for (int ms = 0; ms < 2; ms++) {
        int rA = rowBase + rowOff + ms * 16 + grp;
        int rB = rA + 8;
        float sA = (rA < M) ? rsqrtf(fmaxf(rs[rA], 1.0f)) : 0.f;
        float sB = (rB < M) ? rsqrtf(fmaxf(rs[rB], 1.0f)) : 0.f;
#pragma unroll
        for (int ns = 0; ns < 8; ns++) {
            int cC = colOff + ns * 8 + 2 * tig;
            if (rA < M) {
                float2 o = make_float2(acc[ms][ns].x * sA, acc[ms][ns].y * sA);
                *(float2*)(C + (size_t)rA * 128 + cC) = o;
            }
            if (rB < M) {
                float2 o = make_float2(acc[ms][ns].z * sB, acc[ms][ns].w * sB);
                *(float2*)(C + (size_t)rB * 128 + cC) = o;
            }
        }
    }
}

__global__ __launch_bounds__(256, 2) void att_gemm_f16(
    const float* __restrict__ Z1, const float* __restrict__ Z2,
    const float* __restrict__ W,
    const float* __restrict__ bb, const float* __restrict__ qq,
    float* __restrict__ wsum, int M) {
    const float* A = blockIdx.y == 0 ? Z1 : Z2;

    GEMM_PROLOGUE()
    GEMM_MAINLOOP()

    float p = 0.f;
#pragma unroll
    for (int ms = 0; ms < 2; ms++) {
        int rA = rowBase + rowOff + ms * 16 + grp;
        int rB = rA + 8;
#pragma unroll
        for (int ns = 0; ns < 8; ns++) {
            int cC = colOff + ns * 8 + 2 * tig;
            float b0v = __ldg(bb + cC), b1v = __ldg(bb + cC + 1);
            float q0v = __ldg(qq + cC), q1v = __ldg(qq + cC + 1);
            if (rA < M)
                p += tanhf(acc[ms][ns].x + b0v) * q0v + tanhf(acc[ms][ns].y + b1v) * q1v;
            if (rB < M)
                p += tanhf(acc[ms][ns].z + b0v) * q0v + tanhf(acc[ms][ns].w + b1v) * q1v;
        }
    }
#pragma unroll
    for (int o = 16; o > 0; o >>= 1) p += __shfl_xor_sync(0xffffffffu, p, o);
    if (lane == 0) atomicAdd(wsum + blockIdx.y, p);
}

// ---------------- column moments (merged: y=0 paper, y=1 author) -------------
__global__ __launch_bounds__(128) void stats_kernel(
    const float* __restrict__ z1, const float* __restrict__ z2,
    const float* __restrict__ z3, int MP, int MA) {
    int c = threadIdx.x;
    if (blockIdx.y == 0) {
        int r0 = blockIdx.x * 128;
        int r1 = min(r0 + 128, MP);
        if (r0 >= MP) return;
        float s1 = 0.f, s2 = 0.f, q1 = 0.f, q2 = 0.f, cx = 0.f;
        for (int r = r0; r < r1; r++) {
            float v1 = z1[(size_t)r * 128 + c];
            float v2 = z2[(size_t)r * 128 + c];
            s1 += v1; s2 += v2; q1 += v1 * v1; q2 += v2 * v2; cx += v1 * v2;
        }
        atomicAdd(&g_stats[0 * 128 + c], s1);
        atomicAdd(&g_stats[1 * 128 + c], s2);
        atomicAdd(&g_stats[2 * 128 + c], q1);
        atomicAdd(&g_stats[3 * 128 + c], q2);
        atomicAdd(&g_stats[4 * 128 + c], cx);
    } else {
        int r0 = blockIdx.x * 128;
        int r1 = min(r0 + 128, MA);
        if (r0 >= MA) return;
        float s3 = 0.f, q3 = 0.f;
        for (int r = r0; r < r1; r++) {
            float v = z3[(size_t)r * 128 + c];
            s3 += v; q3 += v * v;
        }
        atomicAdd(&g_stats[5 * 128 + c], s3);
        atomicAdd(&g_stats[6 * 128 + c], q3);
    }
}

// ---------------- finalize ----------------
__global__ void finalize_kernel(const float* __restrict__ gamma, const float* __restrict__ betaBN,
                                int MP, int MA) {
    int j = threadIdx.x;
    float w1 = g_wsum[0] / (float)MP;
    float w2 = g_wsum[1] / (float)MP;
    float m = fmaxf(w1, w2);
    float e1 = expf(w1 - m), e2 = expf(w2 - m);
    float b1 = e1 / (e1 + e2), b2 = e2 / (e1 + e2);
    if (j == 0) { g_beta[0] = b1; g_beta[1] = b2; }

    float S1 = g_stats[0 * 128 + j], S2 = g_stats[1 * 128 + j];
    float Q1 = g_stats[2 * 128 + j], Q2 = g_stats[3 * 128 + j];
    float CX = g_stats[4 * 128 + j];
    float S3 = g_stats[5 * 128 + j], Q3 = g_stats[6 * 128 + j];

    float invMP = 1.0f / (float)MP;
    float mu = (b1 * S1 + b2 * S2) * invMP;
    float ex2 = (b1 * b1 * Q1 + 2.f * b1 * b2 * CX + b2 * b2 * Q2) * invMP;
    float var = ex2 - mu * mu;
    float sc = gamma[j] * rsqrtf(var + 1e-5f);
    g_scale_p[j] = sc;
    g_shift_p[j] = betaBN[j] - mu * sc;

    float invMA = 1.0f / (float)MA;
    float mua = S3 * invMA;
    float vara = Q3 * invMA - mua * mua;
    float sca = gamma[j] * rsqrtf(vara + 1e-5f);
    g_scale_a[j] = sca;
    g_shift_a[j] = betaBN[j] - mua * sca;
}

// -------- combine + BN + row L2 normalize (merged: y=0 paper, y=1 author) ----
__global__ __launch_bounds__(256) void out_kernel(
    const float* __restrict__ z1, const float* __restrict__ z2,
    const float* __restrict__ z3, float* __restrict__ out, int MP, int MA) {
    int gt = blockIdx.x * blockDim.x + threadIdx.x;
    int row = gt >> 5, lane = gt & 31;
    float4 y;
    float* o;
    if (blockIdx.y == 0) {
        if (row >= MP) return;
        float b1 = g_beta[0], b2 = g_beta[1];
        float4 v1 = *((const float4*)(z1 + (size_t)row * 128) + lane);
        float4 v2 = *((const float4*)(z2 + (size_t)row * 128) + lane);
        float4 sc = *(const float4*)&g_scale_p[lane * 4];
        float4 sh = *(const float4*)&g_shift_p[lane * 4];
        y.x = (b1 * v1.x + b2 * v2.x) * sc.x + sh.x;
        y.y = (b1 * v1.y + b2 * v2.y) * sc.y + sh.y;
        y.z = (b1 * v1.z + b2 * v2.z) * sc.z + sh.z;
        y.w = (b1 * v1.w + b2 * v2.w) * sc.w + sh.w;
        o = out + (size_t)row * 128;
    } else {
        if (row >= MA) return;
        float4 v = *((const float4*)(z3 + (size_t)row * 128) + lane);
        float4 sc = *(const float4*)&g_scale_a[lane * 4];
        float4 sh = *(const float4*)&g_shift_a[lane * 4];
        y.x = v.x * sc.x + sh.x;
        y.y = v.y * sc.y + sh.y;
        y.z = v.z * sc.z + sh.z;
        y.w = v.w * sc.w + sh.w;
        o = out + (size_t)(MP + row) * 128;
    }
    float ss = y.x * y.x + y.y * y.y + y.z * y.z + y.w * y.w;
#pragma unroll
    for (int off = 16; off > 0; off >>= 1) ss += __shfl_xor_sync(0xffffffffu, ss, off);
    float inv = rsqrtf(ss + 1e-12f);
    ((float4*)o)[lane] = make_float4(y.x * inv, y.y * inv, y.z * inv, y.w * inv);
}

// ---------------- launch ----------------
extern "C" void kernel_launch(void* const* d_in, const int* in_sizes, int n_in,
                              void* d_out, int out_size) {
    const float* h_paper  = (const float*)d_in[0];
    const float* h_author = (const float*)d_in[1];
    const float* W1   = (const float*)d_in[2];
    const float* W2   = (const float*)d_in[3];
    const float* W3   = (const float*)d_in[4];
    const float* attW = (const float*)d_in[5];
    const float* attb = (const float*)d_in[6];
    const float* attq = (const float*)d_in[7];
    const float* gamma  = (const float*)d_in[8];
    const float* betaBN = (const float*)d_in[9];
    const int* s1 = (const int*)d_in[10];
    const int* d1 = (const int*)d_in[11];
    const int* s2 = (const int*)d_in[12];
    const int* d2 = (const int*)d_in[13];
    const int* s3 = (const int*)d_in[14];
    const int* d3 = (const int*)d_in[15];
    float* out = (float*)d_out;

    const int MP = in_sizes[0] / Dv;
    const int MA = in_sizes[1] / Dv;
    const int E  = in_sizes[10];

    float *agg1, *agg2, *agg3, *z1, *z2, *z3, *deg, *wsum;
    cudaGetSymbolAddress((void**)&agg1, g_agg1);
    cudaGetSymbolAddress((void**)&agg2, g_agg2);
    cudaGetSymbolAddress((void**)&agg3, g_agg3);
    cudaGetSymbolAddress((void**)&z1, g_z1);
    cudaGetSymbolAddress((void**)&z2, g_z2);
    cudaGetSymbolAddress((void**)&z3, g_z3);
    cudaGetSymbolAddress((void**)&deg, g_deg);
    cudaGetSymbolAddress((void**)&wsum, g_wsum);

    // 1. init: fp16 table + zero deg/stats/wsum (merged)
    {
        size_t n8 = (size_t)(MP + MA) * Dv / 8;
        init_kernel<<<(int)((n8 + 255) / 256), 256>>>(h_paper, h_author);
    }
    // 2. degrees (raw counts)
    degree_kernel<<<(E + 255) / 256, 256>>>(s1, d1, s2, d2, s3, d3, E);
    // 3. CSR build: 3-phase chunked scan + fill
    {
        int nb = (MP + 255) / 256;   // == 196
        dim3 g1(nb, 3);
        prefix1_kernel<<<g1, 256>>>(MP);
        prefix2_kernel<<<3, 256>>>(nb);
        prefix3_kernel<<<g1, 256>>>(MP);
        dim3 gf((E + 255) / 256, 3);
        fill_kernel<<<gf, 256>>>(s1, d1, s2, d2, s3, d3, E);
    }
    // 4. scatter: warp per dst row, 4-edge chunks
    {
        dim3 g((MP * 32 + 255) / 256, 3);
        scatter_kernel<<<g, 256>>>(MP);
    }
    // 5. conv GEMMs + attention GEMMs (fp16 m16n8k16, single-buffered)
    {
        dim3 g((MP + 127) / 128, 3);
        conv_gemm_f16<<<g, 256>>>(agg1, agg2, agg3, W1, W2, W3,
                                  deg + 1 * 50000, deg + 3 * 50000, deg + 5 * 50000,
                                  z1, z2, z3, MP);
        dim3 ga((MP + 127) / 128, 2);
        att_gemm_f16<<<ga, 256>>>(z1, z2, attW, attb, attq, wsum, MP);
    }
    // 6. moments, finalize, outputs
    {
        dim3 gs((MP + 127) / 128, 2);
        stats_kernel<<<gs, 128>>>(z1, z2, z3, MP, MA);
    }
    finalize_kernel<<<1, 128>>>(gamma, betaBN, MP, MA);
    {
        dim3 go((MP * 32 + 255) / 256, 2);
        out_kernel<<<go, 256>>>(z1, z2, z3, out, MP, MA);
    }
}